// round 1
// baseline (speedup 1.0000x reference)
#include <cuda_runtime.h>
#include <math.h>

// Problem constants
#define BATCH 2
#define SEQ   2048
#define HID   1024
#define NH    16
#define HD    64
#define M_TOK (BATCH*SEQ)          // 4096
#define QKV_N (3*HID)              // 3072

// Scratch (device globals — no allocation allowed)
__device__ float g_q[BATCH*NH*SEQ*HD];   // [b,h,s,d]
__device__ float g_k[BATCH*NH*SEQ*HD];
__device__ float g_v[BATCH*NH*SEQ*HD];
__device__ float g_ao[M_TOK*HID];        // attention out, [b,s, h*d]

// ----------------------------------------------------------------------------
// Tiled SGEMM: C[M,N] = A[M,K] * B[N,K]^T   (both row-major, K contiguous)
// BM=BN=64, BK=16, 256 threads, 4x4 microtile.
// MODE 1: epilogue scatters into g_q/g_k/g_v (QKV gemm, N=3072)
// MODE 0: A is g_ao, plain write to C (proj gemm)
// ----------------------------------------------------------------------------
template<int MODE>
__global__ __launch_bounds__(256)
void gemm_kernel(const float* __restrict__ A, const float* __restrict__ Bm,
                 float* __restrict__ C, int M, int N, int K)
{
    __shared__ float As[16][64];
    __shared__ float Bs[16][64];

    const float* Ap = (MODE == 0) ? (const float*)g_ao : A;

    const int tid = threadIdx.x;
    const int tx = tid & 15, ty = tid >> 4;
    const int m0 = blockIdx.y * 64, n0 = blockIdx.x * 64;
    const int lr = tid >> 2, lc = (tid & 3) << 2;

    float acc[4][4] = {};

    for (int k0 = 0; k0 < K; k0 += 16) {
        float4 av = *(const float4*)&Ap[(long long)(m0 + lr) * K + k0 + lc];
        float4 bv = *(const float4*)&Bm[(long long)(n0 + lr) * K + k0 + lc];
        As[lc + 0][lr] = av.x; As[lc + 1][lr] = av.y;
        As[lc + 2][lr] = av.z; As[lc + 3][lr] = av.w;
        Bs[lc + 0][lr] = bv.x; Bs[lc + 1][lr] = bv.y;
        Bs[lc + 2][lr] = bv.z; Bs[lc + 3][lr] = bv.w;
        __syncthreads();
        #pragma unroll
        for (int kk = 0; kk < 16; kk++) {
            float4 a = *(const float4*)&As[kk][ty * 4];
            float4 b = *(const float4*)&Bs[kk][tx * 4];
            acc[0][0] += a.x * b.x; acc[0][1] += a.x * b.y; acc[0][2] += a.x * b.z; acc[0][3] += a.x * b.w;
            acc[1][0] += a.y * b.x; acc[1][1] += a.y * b.y; acc[1][2] += a.y * b.z; acc[1][3] += a.y * b.w;
            acc[2][0] += a.z * b.x; acc[2][1] += a.z * b.y; acc[2][2] += a.z * b.z; acc[2][3] += a.z * b.w;
            acc[3][0] += a.w * b.x; acc[3][1] += a.w * b.y; acc[3][2] += a.w * b.z; acc[3][3] += a.w * b.w;
        }
        __syncthreads();
    }

    #pragma unroll
    for (int i = 0; i < 4; i++) {
        int m = m0 + ty * 4 + i;
        #pragma unroll
        for (int j = 0; j < 4; j++) {
            int n = n0 + tx * 4 + j;
            float v = acc[i][j];
            if (MODE == 0) {
                C[(long long)m * N + n] = v;
            } else {
                int which = n >> 10;          // 0=q 1=k 2=v
                int rem = n & 1023;
                int h = rem >> 6, d = rem & 63;
                int b = m >> 11, s = m & 2047;
                float* dst = (which == 0) ? g_q : (which == 1) ? g_k : g_v;
                dst[((((long long)b * NH + h) * SEQ) + s) * HD + d] = v;
            }
        }
    }
}

// ----------------------------------------------------------------------------
// RoPE on first 32 dims of q and k. Pair (i, i+16), i in [0,16), plus the
// independent second half-pair indices i+16 use their own freq.
// inv_freq[i] = 10000^(-i/32), angle = s * inv_freq (match jax fp32 pipeline).
// ----------------------------------------------------------------------------
__global__ __launch_bounds__(256)
void rope_kernel()
{
    int idx = blockIdx.x * blockDim.x + threadIdx.x;   // BATCH*NH*SEQ*16
    int i  = idx & 15;
    int s  = (idx >> 4) & 2047;
    int bh = idx >> 15;
    long long base = ((long long)bh * SEQ + s) * HD;

    const double li = 0.2878231366242557;  // ln(10000)/32
    float invf1 = (float)exp(-(double)i * li);
    float invf2 = (float)exp(-(double)(i + 16) * li);
    float a1 = (float)s * invf1;
    float a2 = (float)s * invf2;
    float c1 = cosf(a1), s1 = sinf(a1);
    float c2 = cosf(a2), s2 = sinf(a2);

    float qa = g_q[base + i], qb = g_q[base + i + 16];
    g_q[base + i]      = qa * c1 - qb * s1;
    g_q[base + i + 16] = qb * c2 + qa * s2;

    float ka = g_k[base + i], kb = g_k[base + i + 16];
    g_k[base + i]      = ka * c1 - kb * s1;
    g_k[base + i + 16] = kb * c2 + ka * s2;
}

// ----------------------------------------------------------------------------
// Flash-style attention. Block = 256 threads, handles 64 query rows of one
// (b,h). Loops over 32 key tiles of 64. Q row kept in registers. Online
// softmax; 4 threads per row (thread t -> row=t&63, dim-group g=t>>6).
// ----------------------------------------------------------------------------
__global__ __launch_bounds__(256)
void attn_kernel()
{
    extern __shared__ float sm[];
    float* Ks   = sm;            // 64*64
    float* Vs   = sm + 4096;     // 64*64
    float* Ss   = sm + 8192;     // 64*65 (Q staging, then probabilities)
    float* redA = sm + 12352;    // 4*64
    float* redB = sm + 12608;    // 4*64   total 12864 floats

    const int tid = threadIdx.x;
    const int row = tid & 63, g = tid >> 6;
    const int q0 = blockIdx.x * 64;
    const int bh = blockIdx.y;
    const long long qbase = ((long long)bh * SEQ + q0) * HD;

    // stage Q tile (coalesced) then pull this thread's row into registers
    for (int idx = tid; idx < 4096; idx += 256)
        Ss[(idx >> 6) * 65 + (idx & 63)] = g_q[qbase + idx];
    __syncthreads();
    float qreg[64];
    #pragma unroll
    for (int d = 0; d < 64; d++) qreg[d] = Ss[row * 65 + d];

    float m = -1e30f, l = 0.f;
    float acc[16] = {};

    for (int kt = 0; kt < 32; kt++) {
        const long long kb = ((long long)bh * SEQ + kt * 64) * HD;
        __syncthreads();                       // prior tile fully consumed
        for (int idx = tid; idx < 4096; idx += 256) {
            Ks[idx] = g_k[kb + idx];
            Vs[idx] = g_v[kb + idx];
        }
        __syncthreads();

        // scores for this thread's 16 keys
        float sc[16];
        float smax = -1e30f;
        #pragma unroll
        for (int jj = 0; jj < 16; jj++) {
            int j = g * 16 + jj;
            const float4* kp = (const float4*)&Ks[j * 64];
            float s = 0.f;
            #pragma unroll
            for (int d4 = 0; d4 < 16; d4++) {
                float4 kv = kp[d4];
                s += qreg[d4*4]   * kv.x + qreg[d4*4+1] * kv.y
                   + qreg[d4*4+2] * kv.z + qreg[d4*4+3] * kv.w;
            }
            s *= 0.125f;
            sc[jj] = s;
            smax = fmaxf(smax, s);
        }
        redA[g * 64 + row] = smax;
        __syncthreads();

        float mt = fmaxf(fmaxf(redA[row], redA[64 + row]),
                         fmaxf(redA[128 + row], redA[192 + row]));
        float mnew = fmaxf(m, mt);
        float corr = expf(m - mnew);
        float psum = 0.f;
        #pragma unroll
        for (int jj = 0; jj < 16; jj++) {
            float p = expf(sc[jj] - mnew);
            psum += p;
            Ss[row * 65 + g * 16 + jj] = p;
        }
        redB[g * 64 + row] = psum;
        #pragma unroll
        for (int k = 0; k < 16; k++) acc[k] *= corr;
        m = mnew;
        __syncthreads();
        l = l * corr + redB[row] + redB[64 + row] + redB[128 + row] + redB[192 + row];

        // PV: accumulate this thread's 16 output dims over all 64 keys
        const int d0 = g * 16;
        #pragma unroll 4
        for (int j = 0; j < 64; j++) {
            float pj = Ss[row * 65 + j];
            const float4* vp = (const float4*)&Vs[j * 64 + d0];
            float4 v0 = vp[0], v1 = vp[1], v2 = vp[2], v3 = vp[3];
            acc[0]  += pj * v0.x; acc[1]  += pj * v0.y; acc[2]  += pj * v0.z; acc[3]  += pj * v0.w;
            acc[4]  += pj * v1.x; acc[5]  += pj * v1.y; acc[6]  += pj * v1.z; acc[7]  += pj * v1.w;
            acc[8]  += pj * v2.x; acc[9]  += pj * v2.y; acc[10] += pj * v2.z; acc[11] += pj * v2.w;
            acc[12] += pj * v3.x; acc[13] += pj * v3.y; acc[14] += pj * v3.z; acc[15] += pj * v3.w;
        }
    }

    float invl = 1.f / l;
    const int b = bh >> 4, h = bh & 15;
    long long ob = ((long long)(b * SEQ + q0 + row)) * HID + h * HD + g * 16;
    #pragma unroll
    for (int k = 0; k < 16; k++) g_ao[ob + k] = acc[k] * invl;
}

// ----------------------------------------------------------------------------
extern "C" void kernel_launch(void* const* d_in, const int* in_sizes, int n_in,
                              void* d_out, int out_size)
{
    const float* x     = (const float*)d_in[0];   // [2,2048,1024]
    const float* Wqkv  = (const float*)d_in[1];   // [3072,1024]
    const float* Wproj = (const float*)d_in[2];   // [1024,1024]
    float* out = (float*)d_out;                   // [2,2048,1024]

    // 1) QKV GEMM + scatter to per-head q/k/v
    gemm_kernel<1><<<dim3(QKV_N / 64, M_TOK / 64), 256>>>(x, Wqkv, nullptr,
                                                          M_TOK, QKV_N, HID);
    // 2) RoPE on q,k
    rope_kernel<<<(BATCH * NH * SEQ * 16) / 256, 256>>>();

    // 3) attention
    const int smem_bytes = 12864 * 4;  // 50.25 KB
    cudaFuncSetAttribute(attn_kernel, cudaFuncAttributeMaxDynamicSharedMemorySize,
                         smem_bytes);
    attn_kernel<<<dim3(SEQ / 64, BATCH * NH), 256, smem_bytes>>>();

    // 4) output projection
    gemm_kernel<0><<<dim3(HID / 64, M_TOK / 64), 256>>>(nullptr, Wproj, out,
                                                        M_TOK, HID, HID);
}